// round 1
// baseline (speedup 1.0000x reference)
#include <cuda_runtime.h>

#define NN   50000
#define EE   800000
#define HH   4
#define CC   32
#define HC   128
#define NGR  64
#define NOUT 10

// ---------------- scratch (device globals; no allocation allowed) ------------
__device__ float g_h[NN * HC];     // GAT: h = x@W ; later: agg buffers
__device__ float g_acc[NN * HC];   // GAT: weighted accumulator ; later: x3
__device__ float g_x[NN * HC];     // current node features between layers
__device__ float g_as[NN * HH];
__device__ float g_ad[NN * HH];
__device__ float g_m[NN * HH];
__device__ float g_z[NN * HH];
__device__ float g_deg[NN];
__device__ float g_pool[NGR * CC];
__device__ float g_cnt[NGR];

__device__ __forceinline__ float lrelu(float v) { return v > 0.f ? v : 0.2f * v; }

__device__ __forceinline__ void atomicMaxF(float* addr, float v) {
    // sign-split trick: valid total order for IEEE floats
    if (v >= 0.f) atomicMax((int*)addr, __float_as_int(v));
    else          atomicMin((unsigned int*)addr, __float_as_uint(v));
}

// ---------------- GEMM: Y(g_h) = X @ W, [N,128]x[128,128] -------------------
__global__ void k_gemm128(const float* __restrict__ X, const float* __restrict__ W) {
    __shared__ float Xs[16][HC];
    int row0 = blockIdx.x * 16;
    int j = threadIdx.x;
#pragma unroll
    for (int r = 0; r < 16; r++) {
        int row = row0 + r;
        Xs[r][j] = (row < NN) ? X[row * HC + j] : 0.f;
    }
    __syncthreads();
    float acc[16];
#pragma unroll
    for (int r = 0; r < 16; r++) acc[r] = 0.f;
#pragma unroll 8
    for (int k = 0; k < HC; k++) {
        float w = W[k * HC + j];
#pragma unroll
        for (int r = 0; r < 16; r++) acc[r] = fmaf(Xs[r][k], w, acc[r]);
    }
#pragma unroll
    for (int r = 0; r < 16; r++) {
        int row = row0 + r;
        if (row < NN) g_h[row * HC + j] = acc[r];
    }
}

// ---------------- attention logits per (node, head) + self-loop max init ----
__global__ void k_attn(const float* __restrict__ aw_s, const float* __restrict__ aw_d) {
    int tid = blockIdx.x * blockDim.x + threadIdx.x;
    if (tid >= NN * HH) return;
    int node = tid >> 2, h = tid & 3;
    const float* hv = g_h + node * HC + h * CC;
    float ss = 0.f, sd = 0.f;
#pragma unroll
    for (int c = 0; c < CC; c++) {
        float v = hv[c];
        ss = fmaf(v, aw_s[h * CC + c], ss);
        sd = fmaf(v, aw_d[h * CC + c], sd);
    }
    g_as[tid] = ss;
    g_ad[tid] = sd;
    g_m[tid] = lrelu(ss + sd);  // self-loop term always present -> init for max
}

// ---------------- per-edge segment max ---------------------------------------
__global__ void k_edge_max(const int* __restrict__ src, const int* __restrict__ dst) {
    int tid = blockIdx.x * blockDim.x + threadIdx.x;
    if (tid >= EE * HH) return;
    int e = tid >> 2, h = tid & 3;
    int s = src[e], d = dst[e];
    atomicMaxF(&g_m[d * HH + h], lrelu(g_as[s * HH + h] + g_ad[d * HH + h]));
}

// ---------------- self-loop: init acc and z (plain writes) -------------------
__global__ void k_selfinit() {
    int tid = blockIdx.x * blockDim.x + threadIdx.x;
    if (tid >= NN * HC) return;
    int node = tid >> 7, j = tid & 127, h = j >> 5;
    float w = expf(lrelu(g_as[node * HH + h] + g_ad[node * HH + h]) - g_m[node * HH + h]);
    g_acc[tid] = w * g_h[tid];
    if ((j & 31) == 0) g_z[node * HH + h] = w;
}

// ---------------- per-edge softmax-weighted aggregation (1 warp / edge) ------
__global__ void k_edge_acc(const int* __restrict__ src, const int* __restrict__ dst) {
    int gt = blockIdx.x * blockDim.x + threadIdx.x;
    int e = gt >> 5;
    if (e >= EE) return;
    int lane = gt & 31;
    int s = src[e], d = dst[e];
    float w[4];
#pragma unroll
    for (int h = 0; h < 4; h++)
        w[h] = expf(lrelu(g_as[s * HH + h] + g_ad[d * HH + h]) - g_m[d * HH + h]);
    if (lane < 4) atomicAdd(&g_z[d * HH + lane], w[lane]);
#pragma unroll
    for (int q = 0; q < 4; q++)
        atomicAdd(&g_acc[d * HC + q * CC + lane], w[q] * g_h[s * HC + q * CC + lane]);
}

// ---------------- finalize: x = relu(acc/z + bias) ---------------------------
__global__ void k_finalize(const float* __restrict__ bias) {
    int tid = blockIdx.x * blockDim.x + threadIdx.x;
    if (tid >= NN * HC) return;
    int node = tid >> 7, j = tid & 127, h = j >> 5;
    float v = g_acc[tid] / (g_z[node * HH + h] + 1e-16f) + bias[j];
    g_x[tid] = fmaxf(v, 0.f);
}

// ---------------- 32-wide GEMMs (post-projection scatter trick) --------------
template <int FIN>
__global__ void k_gemm32(const float* __restrict__ X, const float* __restrict__ W,
                         float* __restrict__ Y) {
    __shared__ float Xs[8][FIN];
    int row0 = blockIdx.x * 8, t = threadIdx.x;
    for (int idx = t; idx < 8 * FIN; idx += 256) {
        int r = idx / FIN, k = idx - r * FIN;
        int row = row0 + r;
        Xs[r][k] = (row < NN) ? X[row * FIN + k] : 0.f;
    }
    __syncthreads();
    int r = t >> 5, c = t & 31, row = row0 + r;
    if (row >= NN) return;
    float s = 0.f;
#pragma unroll 8
    for (int k = 0; k < FIN; k++) s = fmaf(Xs[r][k], W[k * CC + c], s);
    Y[row * CC + c] = s;
}

// Y = relu(X@W + D*scale + bias), scale = 1/max(deg,1) if deg else 1
template <int FIN>
__global__ void k_gemm_add(const float* __restrict__ X, const float* __restrict__ W,
                           const float* __restrict__ D, const float* __restrict__ bias,
                           const float* __restrict__ deg, float* __restrict__ Y) {
    __shared__ float Xs[8][FIN];
    int row0 = blockIdx.x * 8, t = threadIdx.x;
    for (int idx = t; idx < 8 * FIN; idx += 256) {
        int r = idx / FIN, k = idx - r * FIN;
        int row = row0 + r;
        Xs[r][k] = (row < NN) ? X[row * FIN + k] : 0.f;
    }
    __syncthreads();
    int r = t >> 5, c = t & 31, row = row0 + r;
    if (row >= NN) return;
    float s = 0.f;
#pragma unroll 8
    for (int k = 0; k < FIN; k++) s = fmaf(Xs[r][k], W[k * CC + c], s);
    float dscale = deg ? (1.f / fmaxf(deg[row], 1.f)) : 1.f;
    Y[row * CC + c] = fmaxf(s + D[row * CC + c] * dscale + bias[c], 0.f);
}

// ---------------- 32-wide edge scatter (optionally count degree) -------------
__global__ void k_scatter32(const int* __restrict__ src, const int* __restrict__ dst,
                            const float* __restrict__ P, float* __restrict__ Agg,
                            int computeDeg) {
    int tid = blockIdx.x * blockDim.x + threadIdx.x;
    int e = tid >> 5;
    if (e >= EE) return;
    int j = tid & 31;
    int s = src[e], d = dst[e];
    atomicAdd(&Agg[d * CC + j], P[s * CC + j]);
    if (computeDeg && j == 0) atomicAdd(&g_deg[d], 1.f);
}

// ---------------- global mean pool -------------------------------------------
__global__ void k_pool(const int* __restrict__ batch, const float* __restrict__ X) {
    int tid = blockIdx.x * blockDim.x + threadIdx.x;
    if (tid >= NN * CC) return;
    int node = tid >> 5, c = tid & 31;
    int b = batch[node];
    atomicAdd(&g_pool[b * CC + c], X[node * CC + c]);
    if (c == 0) atomicAdd(&g_cnt[b], 1.f);
}

// ---------------- MLP head (single tiny block) -------------------------------
__global__ void k_head(const float* __restrict__ Wf1, const float* __restrict__ bf1,
                       const float* __restrict__ Wf2, const float* __restrict__ bf2,
                       float* __restrict__ out) {
    __shared__ float t1[NGR * CC];
    int t = threadIdx.x;
    for (int idx = t; idx < NGR * CC; idx += blockDim.x) {
        int g = idx >> 5, c = idx & 31;
        float inv = 1.f / fmaxf(g_cnt[g], 1.f);
        float s = 0.f;
#pragma unroll
        for (int k = 0; k < CC; k++) s = fmaf(g_pool[g * CC + k] * inv, Wf1[k * CC + c], s);
        t1[idx] = fmaxf(s + bf1[c], 0.f);
    }
    __syncthreads();
    for (int idx = t; idx < NGR * NOUT; idx += blockDim.x) {
        int g = idx / NOUT, o = idx - g * NOUT;
        float s = 0.f;
#pragma unroll
        for (int k = 0; k < CC; k++) s = fmaf(t1[g * CC + k], Wf2[k * NOUT + o], s);
        out[idx] = s + bf2[o];
    }
}

// =============================================================================
extern "C" void kernel_launch(void* const* d_in, const int* in_sizes, int n_in,
                              void* d_out, int out_size) {
    const float* x   = (const float*)d_in[0];
    const int*   ei  = (const int*)d_in[1];
    const int*   bat = (const int*)d_in[2];
    const float* W1  = (const float*)d_in[3];
    const float* as1 = (const float*)d_in[4];
    const float* ad1 = (const float*)d_in[5];
    const float* b1  = (const float*)d_in[6];
    const float* W2  = (const float*)d_in[7];
    const float* as2 = (const float*)d_in[8];
    const float* ad2 = (const float*)d_in[9];
    const float* b2  = (const float*)d_in[10];
    const float* W3r = (const float*)d_in[11];
    const float* W3l = (const float*)d_in[12];
    const float* b3  = (const float*)d_in[13];
    const float* W4l = (const float*)d_in[14];
    const float* b4l = (const float*)d_in[15];
    const float* W4r = (const float*)d_in[16];
    const float* Wf1 = (const float*)d_in[17];
    const float* bf1 = (const float*)d_in[18];
    const float* Wf2 = (const float*)d_in[19];
    const float* bf2 = (const float*)d_in[20];
    const int* src = ei;
    const int* dst = ei + EE;
    float* out = (float*)d_out;

    static float *p_h = nullptr, *p_acc, *p_x, *p_deg, *p_pool, *p_cnt;
    if (!p_h) {
        cudaGetSymbolAddress((void**)&p_h, g_h);
        cudaGetSymbolAddress((void**)&p_acc, g_acc);
        cudaGetSymbolAddress((void**)&p_x, g_x);
        cudaGetSymbolAddress((void**)&p_deg, g_deg);
        cudaGetSymbolAddress((void**)&p_pool, g_pool);
        cudaGetSymbolAddress((void**)&p_cnt, g_cnt);
    }

    const int T = 256;
    const int gNH  = (NN * HH + T - 1) / T;
    const int gEH  = (EE * HH + T - 1) / T;
    const int gNHC = (NN * HC + T - 1) / T;
    const int gEW  = (EE * 32 + T - 1) / T;   // warp per edge

    // ---- GAT layer 1 ----
    k_gemm128<<<(NN + 15) / 16, 128>>>(x, W1);
    k_attn<<<gNH, T>>>(as1, ad1);
    k_edge_max<<<gEH, T>>>(src, dst);
    k_selfinit<<<gNHC, T>>>();
    k_edge_acc<<<gEW, T>>>(src, dst);
    k_finalize<<<gNHC, T>>>(b1);

    // ---- GAT layer 2 ----
    k_gemm128<<<(NN + 15) / 16, 128>>>(p_x, W2);
    k_attn<<<gNH, T>>>(as2, ad2);
    k_edge_max<<<gEH, T>>>(src, dst);
    k_selfinit<<<gNHC, T>>>();
    k_edge_acc<<<gEW, T>>>(src, dst);
    k_finalize<<<gNHC, T>>>(b2);

    // ---- GraphConv: x3 = relu(segsum(x2[src])@W3r + b3 + x2@W3l) ----
    // project first, then 32-wide scatter: segsum(x2[src])@W3r == segsum((x2@W3r)[src])
    k_gemm32<HC><<<(NN + 7) / 8, 256>>>(p_x, W3r, p_acc);          // P = x2@W3r
    cudaMemsetAsync(p_h, 0, (size_t)NN * CC * sizeof(float));
    cudaMemsetAsync(p_deg, 0, (size_t)NN * sizeof(float));
    k_scatter32<<<gEW, T>>>(src, dst, p_acc, p_h, 1);              // agg + deg
    k_gemm_add<HC><<<(NN + 7) / 8, 256>>>(p_x, W3l, p_h, b3, nullptr, p_acc);  // x3

    // ---- SAGEConv: x4 = relu(mean@W4l + b4l + x3@W4r), mean scatter after proj
    k_gemm32<CC><<<(NN + 7) / 8, 256>>>(p_acc, W4l, p_x);          // P2 = x3@W4l
    cudaMemsetAsync(p_h, 0, (size_t)NN * CC * sizeof(float));
    k_scatter32<<<gEW, T>>>(src, dst, p_x, p_h, 0);                // agg2
    k_gemm_add<CC><<<(NN + 7) / 8, 256>>>(p_acc, W4r, p_h, b4l, p_deg, p_x);   // x4

    // ---- pool + head ----
    cudaMemsetAsync(p_pool, 0, NGR * CC * sizeof(float));
    cudaMemsetAsync(p_cnt, 0, NGR * sizeof(float));
    k_pool<<<(NN * CC + T - 1) / T, T>>>(bat, p_x);
    k_head<<<1, 1024>>>(Wf1, bf1, Wf2, bf2, out);
}

// round 2
// speedup vs baseline: 1.3568x; 1.3568x over previous
#include <cuda_runtime.h>

#define NN   50000
#define EE   800000
#define HH   4
#define CC   32
#define HC   128
#define NGR  64
#define NOUT 10

// ---------------- scratch (device globals; no allocation allowed) ------------
__device__ float g_h[NN * HC];     // GAT: h = x@W ; later: proj buffers
__device__ float g_acc[NN * HC];   // GAT: weighted accumulator ; later: x3
__device__ float g_x[NN * HC];     // current node features between layers
__device__ float g_as[NN * HH];
__device__ float g_ad[NN * HH];
__device__ float g_m[NN * HH];
__device__ float g_z[NN * HH];
__device__ float g_deg[NN];
__device__ float g_pool[NGR * CC];
__device__ float g_cnt[NGR];

__device__ __forceinline__ float lrelu(float v) { return v > 0.f ? v : 0.2f * v; }

__device__ __forceinline__ void atomicMaxF(float* addr, float v) {
    if (v >= 0.f) atomicMax((int*)addr, __float_as_int(v));
    else          atomicMin((unsigned int*)addr, __float_as_uint(v));
}

// ---------------- GEMM: Y(g_h) = X @ W, [N,128]x[128,128] -------------------
__global__ void k_gemm128(const float* __restrict__ X, const float* __restrict__ W) {
    __shared__ float Xs[16][HC];
    int row0 = blockIdx.x * 16;
    int j = threadIdx.x;
#pragma unroll
    for (int r = 0; r < 16; r++) {
        int row = row0 + r;
        Xs[r][j] = (row < NN) ? X[row * HC + j] : 0.f;
    }
    __syncthreads();
    float acc[16];
#pragma unroll
    for (int r = 0; r < 16; r++) acc[r] = 0.f;
#pragma unroll 8
    for (int k = 0; k < HC; k++) {
        float w = W[k * HC + j];
#pragma unroll
        for (int r = 0; r < 16; r++) acc[r] = fmaf(Xs[r][k], w, acc[r]);
    }
#pragma unroll
    for (int r = 0; r < 16; r++) {
        int row = row0 + r;
        if (row < NN) g_h[row * HC + j] = acc[r];
    }
}

// ---------------- attention logits per (node, head) + self-loop max init ----
__global__ void k_attn(const float* __restrict__ aw_s, const float* __restrict__ aw_d) {
    int tid = blockIdx.x * blockDim.x + threadIdx.x;
    if (tid >= NN * HH) return;
    int node = tid >> 2, h = tid & 3;
    const float4* hv = reinterpret_cast<const float4*>(g_h + node * HC + h * CC);
    const float4* ws = reinterpret_cast<const float4*>(aw_s) + h * 8;
    const float4* wd = reinterpret_cast<const float4*>(aw_d) + h * 8;
    float ss = 0.f, sd = 0.f;
#pragma unroll
    for (int i = 0; i < 8; i++) {
        float4 v = hv[i], a = ws[i], b = wd[i];
        ss = fmaf(v.x, a.x, fmaf(v.y, a.y, fmaf(v.z, a.z, fmaf(v.w, a.w, ss))));
        sd = fmaf(v.x, b.x, fmaf(v.y, b.y, fmaf(v.z, b.z, fmaf(v.w, b.w, sd))));
    }
    g_as[tid] = ss;
    g_ad[tid] = sd;
    g_m[tid] = lrelu(ss + sd);  // self-loop term always present -> init for max
}

// ---------------- per-edge segment max (1 thread / edge, all heads) ----------
__global__ void k_edge_max(const int* __restrict__ src, const int* __restrict__ dst) {
    int e = blockIdx.x * blockDim.x + threadIdx.x;
    if (e >= EE) return;
    int s = src[e], d = dst[e];
    float4 a = reinterpret_cast<const float4*>(g_as)[s];
    float4 b = reinterpret_cast<const float4*>(g_ad)[d];
    float* mp = g_m + d * HH;
    atomicMaxF(mp + 0, lrelu(a.x + b.x));
    atomicMaxF(mp + 1, lrelu(a.y + b.y));
    atomicMaxF(mp + 2, lrelu(a.z + b.z));
    atomicMaxF(mp + 3, lrelu(a.w + b.w));
}

// ---------------- per-edge softmax-weighted aggregation (1 warp / edge) ------
// acc & z are pre-zeroed; self-loop folded into finalize.
__global__ void k_edge_acc(const int* __restrict__ src, const int* __restrict__ dst) {
    int gt = blockIdx.x * blockDim.x + threadIdx.x;
    int e = gt >> 5;
    if (e >= EE) return;
    int lane = gt & 31;
    int s = src[e], d = dst[e];
    float w = 0.f;
    if (lane < 4) {
        w = expf(lrelu(g_as[s * HH + lane] + g_ad[d * HH + lane]) - g_m[d * HH + lane]);
        atomicAdd(&g_z[d * HH + lane], w);
    }
    float wh = __shfl_sync(0xffffffffu, w, lane >> 3);
    float4 hv = reinterpret_cast<const float4*>(g_h)[s * 32 + lane];
    float4 v = make_float4(wh * hv.x, wh * hv.y, wh * hv.z, wh * hv.w);
    atomicAdd(reinterpret_cast<float4*>(g_acc) + d * 32 + lane, v);
}

// ---------------- finalize: x = relu((acc + w_self*h)/(z + w_self) + bias) ---
__global__ void k_finalize(const float* __restrict__ bias) {
    int tid = blockIdx.x * blockDim.x + threadIdx.x;
    if (tid >= NN * 32) return;
    int node = tid >> 5, j = tid & 31, h = j >> 3;
    float as = g_as[node * HH + h], ad = g_ad[node * HH + h], m = g_m[node * HH + h];
    float ws = expf(lrelu(as + ad) - m);
    float inv = 1.f / (g_z[node * HH + h] + ws + 1e-16f);
    float4 a = reinterpret_cast<const float4*>(g_acc)[tid];
    float4 hv = reinterpret_cast<const float4*>(g_h)[tid];
    float4 b = reinterpret_cast<const float4*>(bias)[j];
    float4 r;
    r.x = fmaxf(fmaf(ws, hv.x, a.x) * inv + b.x, 0.f);
    r.y = fmaxf(fmaf(ws, hv.y, a.y) * inv + b.y, 0.f);
    r.z = fmaxf(fmaf(ws, hv.z, a.z) * inv + b.z, 0.f);
    r.w = fmaxf(fmaf(ws, hv.w, a.w) * inv + b.w, 0.f);
    reinterpret_cast<float4*>(g_x)[tid] = r;
}

// ---------------- 32-wide GEMMs (post-projection scatter trick) --------------
template <int FIN>
__global__ void k_gemm32(const float* __restrict__ X, const float* __restrict__ W,
                         float* __restrict__ Y) {
    __shared__ float Xs[8][FIN];
    int row0 = blockIdx.x * 8, t = threadIdx.x;
    for (int idx = t; idx < 8 * FIN; idx += 256) {
        int r = idx / FIN, k = idx - r * FIN;
        int row = row0 + r;
        Xs[r][k] = (row < NN) ? X[row * FIN + k] : 0.f;
    }
    __syncthreads();
    int r = t >> 5, c = t & 31, row = row0 + r;
    if (row >= NN) return;
    float s = 0.f;
#pragma unroll 8
    for (int k = 0; k < FIN; k++) s = fmaf(Xs[r][k], W[k * CC + c], s);
    Y[row * CC + c] = s;
}

// Y = relu(X@W + D*scale + bias), scale = 1/max(deg,1) if deg else 1
template <int FIN>
__global__ void k_gemm_add(const float* __restrict__ X, const float* __restrict__ W,
                           const float* __restrict__ D, const float* __restrict__ bias,
                           const float* __restrict__ deg, float* __restrict__ Y) {
    __shared__ float Xs[8][FIN];
    int row0 = blockIdx.x * 8, t = threadIdx.x;
    for (int idx = t; idx < 8 * FIN; idx += 256) {
        int r = idx / FIN, k = idx - r * FIN;
        int row = row0 + r;
        Xs[r][k] = (row < NN) ? X[row * FIN + k] : 0.f;
    }
    __syncthreads();
    int r = t >> 5, c = t & 31, row = row0 + r;
    if (row >= NN) return;
    float s = 0.f;
#pragma unroll 8
    for (int k = 0; k < FIN; k++) s = fmaf(Xs[r][k], W[k * CC + c], s);
    float dscale = deg ? (1.f / fmaxf(deg[row], 1.f)) : 1.f;
    Y[row * CC + c] = fmaxf(s + D[row * CC + c] * dscale + bias[c], 0.f);
}

// ---------------- 32-wide edge scatter (8 lanes/edge, float4 atomics) --------
__global__ void k_scatter32(const int* __restrict__ src, const int* __restrict__ dst,
                            const float* __restrict__ P, float* __restrict__ Agg,
                            int computeDeg) {
    int tid = blockIdx.x * blockDim.x + threadIdx.x;
    int e = tid >> 3;
    if (e >= EE) return;
    int j = tid & 7;
    int s = src[e], d = dst[e];
    float4 p = reinterpret_cast<const float4*>(P)[s * 8 + j];
    atomicAdd(reinterpret_cast<float4*>(Agg) + d * 8 + j, p);
    if (computeDeg && j == 0) atomicAdd(&g_deg[d], 1.f);
}

// ---------------- global mean pool (8 lanes/node, float4 atomics) ------------
__global__ void k_pool(const int* __restrict__ batch, const float* __restrict__ X) {
    int tid = blockIdx.x * blockDim.x + threadIdx.x;
    if (tid >= NN * 8) return;
    int node = tid >> 3, c = tid & 7;
    int b = batch[node];
    float4 v = reinterpret_cast<const float4*>(X)[node * 8 + c];
    atomicAdd(reinterpret_cast<float4*>(g_pool) + b * 8 + c, v);
    if (c == 0) atomicAdd(&g_cnt[b], 1.f);
}

// ---------------- MLP head (single tiny block) -------------------------------
__global__ void k_head(const float* __restrict__ Wf1, const float* __restrict__ bf1,
                       const float* __restrict__ Wf2, const float* __restrict__ bf2,
                       float* __restrict__ out) {
    __shared__ float t1[NGR * CC];
    int t = threadIdx.x;
    for (int idx = t; idx < NGR * CC; idx += blockDim.x) {
        int g = idx >> 5, c = idx & 31;
        float inv = 1.f / fmaxf(g_cnt[g], 1.f);
        float s = 0.f;
#pragma unroll
        for (int k = 0; k < CC; k++) s = fmaf(g_pool[g * CC + k] * inv, Wf1[k * CC + c], s);
        t1[idx] = fmaxf(s + bf1[c], 0.f);
    }
    __syncthreads();
    for (int idx = t; idx < NGR * NOUT; idx += blockDim.x) {
        int g = idx / NOUT, o = idx - g * NOUT;
        float s = 0.f;
#pragma unroll
        for (int k = 0; k < CC; k++) s = fmaf(t1[g * CC + k], Wf2[k * NOUT + o], s);
        out[idx] = s + bf2[o];
    }
}

// =============================================================================
extern "C" void kernel_launch(void* const* d_in, const int* in_sizes, int n_in,
                              void* d_out, int out_size) {
    const float* x   = (const float*)d_in[0];
    const int*   ei  = (const int*)d_in[1];
    const int*   bat = (const int*)d_in[2];
    const float* W1  = (const float*)d_in[3];
    const float* as1 = (const float*)d_in[4];
    const float* ad1 = (const float*)d_in[5];
    const float* b1  = (const float*)d_in[6];
    const float* W2  = (const float*)d_in[7];
    const float* as2 = (const float*)d_in[8];
    const float* ad2 = (const float*)d_in[9];
    const float* b2  = (const float*)d_in[10];
    const float* W3r = (const float*)d_in[11];
    const float* W3l = (const float*)d_in[12];
    const float* b3  = (const float*)d_in[13];
    const float* W4l = (const float*)d_in[14];
    const float* b4l = (const float*)d_in[15];
    const float* W4r = (const float*)d_in[16];
    const float* Wf1 = (const float*)d_in[17];
    const float* bf1 = (const float*)d_in[18];
    const float* Wf2 = (const float*)d_in[19];
    const float* bf2 = (const float*)d_in[20];
    const int* src = ei;
    const int* dst = ei + EE;
    float* out = (float*)d_out;

    static float *p_h = nullptr, *p_acc, *p_x, *p_z, *p_deg, *p_pool, *p_cnt;
    if (!p_h) {
        cudaGetSymbolAddress((void**)&p_h, g_h);
        cudaGetSymbolAddress((void**)&p_acc, g_acc);
        cudaGetSymbolAddress((void**)&p_x, g_x);
        cudaGetSymbolAddress((void**)&p_z, g_z);
        cudaGetSymbolAddress((void**)&p_deg, g_deg);
        cudaGetSymbolAddress((void**)&p_pool, g_pool);
        cudaGetSymbolAddress((void**)&p_cnt, g_cnt);
    }

    const int T = 256;
    const int gNH  = (NN * HH + T - 1) / T;
    const int gE   = (EE + T - 1) / T;
    const int gN32 = (NN * 32 + T - 1) / T;
    const int gEW  = (EE * 32 + T - 1) / T;   // warp per edge
    const int gE8  = (EE * 8 + T - 1) / T;    // 8 lanes per edge

    // ---- GAT layer 1 ----
    k_gemm128<<<(NN + 15) / 16, 128>>>(x, W1);
    cudaMemsetAsync(p_acc, 0, (size_t)NN * HC * sizeof(float));
    cudaMemsetAsync(p_z, 0, (size_t)NN * HH * sizeof(float));
    k_attn<<<gNH, T>>>(as1, ad1);
    k_edge_max<<<gE, T>>>(src, dst);
    k_edge_acc<<<gEW, T>>>(src, dst);
    k_finalize<<<gN32, T>>>(b1);

    // ---- GAT layer 2 ----
    k_gemm128<<<(NN + 15) / 16, 128>>>(p_x, W2);
    cudaMemsetAsync(p_acc, 0, (size_t)NN * HC * sizeof(float));
    cudaMemsetAsync(p_z, 0, (size_t)NN * HH * sizeof(float));
    k_attn<<<gNH, T>>>(as2, ad2);
    k_edge_max<<<gE, T>>>(src, dst);
    k_edge_acc<<<gEW, T>>>(src, dst);
    k_finalize<<<gN32, T>>>(b2);

    // ---- GraphConv: x3 = relu(segsum(x2[src])@W3r + b3 + x2@W3l) ----
    // project first, then 32-wide scatter: segsum(x2[src])@W3r == segsum((x2@W3r)[src])
    k_gemm32<HC><<<(NN + 7) / 8, 256>>>(p_x, W3r, p_acc);          // P = x2@W3r
    cudaMemsetAsync(p_h, 0, (size_t)NN * CC * sizeof(float));
    cudaMemsetAsync(p_deg, 0, (size_t)NN * sizeof(float));
    k_scatter32<<<gE8, T>>>(src, dst, p_acc, p_h, 1);              // agg + deg
    k_gemm_add<HC><<<(NN + 7) / 8, 256>>>(p_x, W3l, p_h, b3, nullptr, p_acc);  // x3

    // ---- SAGEConv: x4 = relu(mean@W4l + b4l + x3@W4r), mean scatter after proj
    k_gemm32<CC><<<(NN + 7) / 8, 256>>>(p_acc, W4l, p_x);          // P2 = x3@W4l
    cudaMemsetAsync(p_h, 0, (size_t)NN * CC * sizeof(float));
    k_scatter32<<<gE8, T>>>(src, dst, p_x, p_h, 0);                // agg2
    k_gemm_add<CC><<<(NN + 7) / 8, 256>>>(p_acc, W4r, p_h, b4l, p_deg, p_x);   // x4

    // ---- pool + head ----
    cudaMemsetAsync(p_pool, 0, NGR * CC * sizeof(float));
    cudaMemsetAsync(p_cnt, 0, NGR * sizeof(float));
    k_pool<<<(NN * 8 + T - 1) / T, T>>>(bat, p_x);
    k_head<<<1, 1024>>>(Wf1, bf1, Wf2, bf2, out);
}

// round 3
// speedup vs baseline: 1.6978x; 1.2514x over previous
#include <cuda_runtime.h>

#define NN   50000
#define EE   800000
#define HH   4
#define CC   32
#define HC   128
#define NGR  64
#define NOUT 10

// ---------------- scratch (device globals; no allocation allowed) ------------
__device__ float g_h[NN * HC];     // GAT: h = x@W ; later: proj buffers
__device__ float g_acc[NN * HC];   // later: x3 / proj
__device__ float g_x[NN * HC];     // current node features between layers
__device__ float g_as[NN * HH];
__device__ float g_ad[NN * HH];
__device__ float g_pool[NGR * CC];
__device__ float g_cnt[NGR];
// CSR by destination
__device__ int g_cnt_i[NN];
__device__ int g_rowptr[NN + 1];
__device__ int g_cursor[NN];
__device__ int g_csrc[EE];

__device__ __forceinline__ float lrelu(float v) { return v > 0.f ? v : 0.2f * v; }

// ---------------- CSR build ---------------------------------------------------
__global__ void k_count(const int* __restrict__ dst) {
    int e = blockIdx.x * blockDim.x + threadIdx.x;
    if (e < EE) atomicAdd(&g_cnt_i[dst[e]], 1);
}

// single-block exclusive scan of g_cnt_i -> g_rowptr, copy to g_cursor
__global__ void k_scan() {
    __shared__ int warpsum[32];
    __shared__ int s_base;
    int t = threadIdx.x;
    if (t == 0) s_base = 0;
    __syncthreads();
    for (int c0 = 0; c0 < NN; c0 += 1024) {
        int i = c0 + t;
        int v = (i < NN) ? g_cnt_i[i] : 0;
        int incl = v;
#pragma unroll
        for (int o = 1; o < 32; o <<= 1) {
            int n = __shfl_up_sync(0xffffffffu, incl, o);
            if ((t & 31) >= o) incl += n;
        }
        if ((t & 31) == 31) warpsum[t >> 5] = incl;
        __syncthreads();
        if (t < 32) {
            int wv = warpsum[t];
#pragma unroll
            for (int o = 1; o < 32; o <<= 1) {
                int n = __shfl_up_sync(0xffffffffu, wv, o);
                if (t >= o) wv += n;
            }
            warpsum[t] = wv;
        }
        __syncthreads();
        int excl = incl - v + ((t >= 32) ? warpsum[(t >> 5) - 1] : 0) + s_base;
        if (i < NN) { g_rowptr[i] = excl; g_cursor[i] = excl; }
        int total = warpsum[31];
        __syncthreads();
        if (t == 0) s_base += total;
        __syncthreads();
    }
    if (t == 0) g_rowptr[NN] = EE;
}

__global__ void k_fill(const int* __restrict__ src, const int* __restrict__ dst) {
    int e = blockIdx.x * blockDim.x + threadIdx.x;
    if (e >= EE) return;
    int pos = atomicAdd(&g_cursor[dst[e]], 1);
    g_csrc[pos] = src[e];
}

// ---------------- GEMM: Y(g_h) = X @ W, [N,128]x[128,128] -------------------
__global__ void k_gemm128(const float* __restrict__ X, const float* __restrict__ W) {
    __shared__ float Xs[16][HC];
    int row0 = blockIdx.x * 16;
    int j = threadIdx.x;
#pragma unroll
    for (int r = 0; r < 16; r++) {
        int row = row0 + r;
        Xs[r][j] = (row < NN) ? X[row * HC + j] : 0.f;
    }
    __syncthreads();
    float acc[16];
#pragma unroll
    for (int r = 0; r < 16; r++) acc[r] = 0.f;
#pragma unroll 8
    for (int k = 0; k < HC; k++) {
        float w = W[k * HC + j];
#pragma unroll
        for (int r = 0; r < 16; r++) acc[r] = fmaf(Xs[r][k], w, acc[r]);
    }
#pragma unroll
    for (int r = 0; r < 16; r++) {
        int row = row0 + r;
        if (row < NN) g_h[row * HC + j] = acc[r];
    }
}

// ---------------- attention logits per (node, head) --------------------------
__global__ void k_attn(const float* __restrict__ aw_s, const float* __restrict__ aw_d) {
    int tid = blockIdx.x * blockDim.x + threadIdx.x;
    if (tid >= NN * HH) return;
    int node = tid >> 2, h = tid & 3;
    const float4* hv = reinterpret_cast<const float4*>(g_h + node * HC + h * CC);
    const float4* ws = reinterpret_cast<const float4*>(aw_s) + h * 8;
    const float4* wd = reinterpret_cast<const float4*>(aw_d) + h * 8;
    float ss = 0.f, sd = 0.f;
#pragma unroll
    for (int i = 0; i < 8; i++) {
        float4 v = hv[i], a = ws[i], b = wd[i];
        ss = fmaf(v.x, a.x, fmaf(v.y, a.y, fmaf(v.z, a.z, fmaf(v.w, a.w, ss))));
        sd = fmaf(v.x, b.x, fmaf(v.y, b.y, fmaf(v.z, b.z, fmaf(v.w, b.w, sd))));
    }
    g_as[tid] = ss;
    g_ad[tid] = sd;
}

// ---------------- fused GAT aggregation: warp per dst node --------------------
// softmax over in-edges (+self loop), weighted sum of h, bias, relu -> g_x
__global__ void k_gat_aggr(const float* __restrict__ bias) {
    int w = (blockIdx.x * blockDim.x + threadIdx.x) >> 5;
    if (w >= NN) return;
    int lane = threadIdx.x & 31;
    int row0 = g_rowptr[w], row1 = g_rowptr[w + 1];
    float4 ad4 = reinterpret_cast<const float4*>(g_ad)[w];
    float4 as_self = reinterpret_cast<const float4*>(g_as)[w];
    // ---- pass 1: per-head max over edges (lane-strided) + self loop ----
    float4 mx;
    mx.x = lrelu(as_self.x + ad4.x);
    mx.y = lrelu(as_self.y + ad4.y);
    mx.z = lrelu(as_self.z + ad4.z);
    mx.w = lrelu(as_self.w + ad4.w);
    for (int k = row0 + lane; k < row1; k += 32) {
        int s = g_csrc[k];
        float4 a = reinterpret_cast<const float4*>(g_as)[s];
        mx.x = fmaxf(mx.x, lrelu(a.x + ad4.x));
        mx.y = fmaxf(mx.y, lrelu(a.y + ad4.y));
        mx.z = fmaxf(mx.z, lrelu(a.z + ad4.z));
        mx.w = fmaxf(mx.w, lrelu(a.w + ad4.w));
    }
#pragma unroll
    for (int o = 16; o; o >>= 1) {
        mx.x = fmaxf(mx.x, __shfl_xor_sync(0xffffffffu, mx.x, o));
        mx.y = fmaxf(mx.y, __shfl_xor_sync(0xffffffffu, mx.y, o));
        mx.z = fmaxf(mx.z, __shfl_xor_sync(0xffffffffu, mx.z, o));
        mx.w = fmaxf(mx.w, __shfl_xor_sync(0xffffffffu, mx.w, o));
    }
    // this lane covers features 4*lane..4*lane+3 -> head = lane>>3
    int hd = lane >> 3;
    float m_l  = (hd == 0) ? mx.x : (hd == 1) ? mx.y : (hd == 2) ? mx.z : mx.w;
    float ad_l = (hd == 0) ? ad4.x : (hd == 1) ? ad4.y : (hd == 2) ? ad4.z : ad4.w;
    // ---- pass 2: serial edge walk, weighted accumulate in registers ----
    float4 acc = make_float4(0.f, 0.f, 0.f, 0.f);
    float z = 0.f;
    int s = (row0 < row1) ? g_csrc[row0] : 0;
    for (int k = row0; k < row1; k++) {
        int s_next = (k + 1 < row1) ? g_csrc[k + 1] : 0;
        float4 a = reinterpret_cast<const float4*>(g_as)[s];
        float4 hv = reinterpret_cast<const float4*>(g_h)[s * 32 + lane];
        float as_l = (hd == 0) ? a.x : (hd == 1) ? a.y : (hd == 2) ? a.z : a.w;
        float wgt = __expf(lrelu(as_l + ad_l) - m_l);
        z += wgt;
        acc.x = fmaf(wgt, hv.x, acc.x);
        acc.y = fmaf(wgt, hv.y, acc.y);
        acc.z = fmaf(wgt, hv.z, acc.z);
        acc.w = fmaf(wgt, hv.w, acc.w);
        s = s_next;
    }
    // ---- self loop ----
    float as_l = (hd == 0) ? as_self.x : (hd == 1) ? as_self.y : (hd == 2) ? as_self.z : as_self.w;
    float wsf = __expf(lrelu(as_l + ad_l) - m_l);
    z += wsf;
    float4 hs = reinterpret_cast<const float4*>(g_h)[w * 32 + lane];
    acc.x = fmaf(wsf, hs.x, acc.x);
    acc.y = fmaf(wsf, hs.y, acc.y);
    acc.z = fmaf(wsf, hs.z, acc.z);
    acc.w = fmaf(wsf, hs.w, acc.w);
    float inv = 1.f / (z + 1e-16f);
    float4 b = reinterpret_cast<const float4*>(bias)[lane];
    float4 r;
    r.x = fmaxf(acc.x * inv + b.x, 0.f);
    r.y = fmaxf(acc.y * inv + b.y, 0.f);
    r.z = fmaxf(acc.z * inv + b.z, 0.f);
    r.w = fmaxf(acc.w * inv + b.w, 0.f);
    reinterpret_cast<float4*>(g_x)[w * 32 + lane] = r;
}

// ---------------- CSR gather for 32-wide features (8 lanes / dst) ------------
__global__ void k_csr_aggr32(const float* __restrict__ P, float* __restrict__ Agg,
                             int mean) {
    int q = (blockIdx.x * blockDim.x + threadIdx.x) >> 3;
    if (q >= NN) return;
    int lane = threadIdx.x & 7;
    int row0 = g_rowptr[q], row1 = g_rowptr[q + 1];
    float4 acc = make_float4(0.f, 0.f, 0.f, 0.f);
    for (int k = row0; k < row1; k++) {
        int s = g_csrc[k];
        float4 p = reinterpret_cast<const float4*>(P)[s * 8 + lane];
        acc.x += p.x; acc.y += p.y; acc.z += p.z; acc.w += p.w;
    }
    if (mean) {
        float inv = 1.f / fmaxf((float)(row1 - row0), 1.f);
        acc.x *= inv; acc.y *= inv; acc.z *= inv; acc.w *= inv;
    }
    reinterpret_cast<float4*>(Agg)[q * 8 + lane] = acc;
}

// ---------------- 32-wide GEMMs ----------------------------------------------
template <int FIN>
__global__ void k_gemm32(const float* __restrict__ X, const float* __restrict__ W,
                         float* __restrict__ Y) {
    __shared__ float Xs[8][FIN];
    int row0 = blockIdx.x * 8, t = threadIdx.x;
    for (int idx = t; idx < 8 * FIN; idx += 256) {
        int r = idx / FIN, k = idx - r * FIN;
        int row = row0 + r;
        Xs[r][k] = (row < NN) ? X[row * FIN + k] : 0.f;
    }
    __syncthreads();
    int r = t >> 5, c = t & 31, row = row0 + r;
    if (row >= NN) return;
    float s = 0.f;
#pragma unroll 8
    for (int k = 0; k < FIN; k++) s = fmaf(Xs[r][k], W[k * CC + c], s);
    Y[row * CC + c] = s;
}

// Y = relu(X@W + D + bias)
template <int FIN>
__global__ void k_gemm_add(const float* __restrict__ X, const float* __restrict__ W,
                           const float* __restrict__ D, const float* __restrict__ bias,
                           float* __restrict__ Y) {
    __shared__ float Xs[8][FIN];
    int row0 = blockIdx.x * 8, t = threadIdx.x;
    for (int idx = t; idx < 8 * FIN; idx += 256) {
        int r = idx / FIN, k = idx - r * FIN;
        int row = row0 + r;
        Xs[r][k] = (row < NN) ? X[row * FIN + k] : 0.f;
    }
    __syncthreads();
    int r = t >> 5, c = t & 31, row = row0 + r;
    if (row >= NN) return;
    float s = 0.f;
#pragma unroll 8
    for (int k = 0; k < FIN; k++) s = fmaf(Xs[r][k], W[k * CC + c], s);
    Y[row * CC + c] = fmaxf(s + D[row * CC + c] + bias[c], 0.f);
}

// ---------------- global mean pool (8 lanes/node, float4 atomics) ------------
__global__ void k_pool(const int* __restrict__ batch, const float* __restrict__ X) {
    int tid = blockIdx.x * blockDim.x + threadIdx.x;
    if (tid >= NN * 8) return;
    int node = tid >> 3, c = tid & 7;
    int b = batch[node];
    float4 v = reinterpret_cast<const float4*>(X)[node * 8 + c];
    atomicAdd(reinterpret_cast<float4*>(g_pool) + b * 8 + c, v);
    if (c == 0) atomicAdd(&g_cnt[b], 1.f);
}

// ---------------- MLP head (single tiny block) -------------------------------
__global__ void k_head(const float* __restrict__ Wf1, const float* __restrict__ bf1,
                       const float* __restrict__ Wf2, const float* __restrict__ bf2,
                       float* __restrict__ out) {
    __shared__ float t1[NGR * CC];
    int t = threadIdx.x;
    for (int idx = t; idx < NGR * CC; idx += blockDim.x) {
        int g = idx >> 5, c = idx & 31;
        float inv = 1.f / fmaxf(g_cnt[g], 1.f);
        float s = 0.f;
#pragma unroll
        for (int k = 0; k < CC; k++) s = fmaf(g_pool[g * CC + k] * inv, Wf1[k * CC + c], s);
        t1[idx] = fmaxf(s + bf1[c], 0.f);
    }
    __syncthreads();
    for (int idx = t; idx < NGR * NOUT; idx += blockDim.x) {
        int g = idx / NOUT, o = idx - g * NOUT;
        float s = 0.f;
#pragma unroll
        for (int k = 0; k < CC; k++) s = fmaf(t1[g * CC + k], Wf2[k * NOUT + o], s);
        out[idx] = s + bf2[o];
    }
}

// =============================================================================
extern "C" void kernel_launch(void* const* d_in, const int* in_sizes, int n_in,
                              void* d_out, int out_size) {
    const float* x   = (const float*)d_in[0];
    const int*   ei  = (const int*)d_in[1];
    const int*   bat = (const int*)d_in[2];
    const float* W1  = (const float*)d_in[3];
    const float* as1 = (const float*)d_in[4];
    const float* ad1 = (const float*)d_in[5];
    const float* b1  = (const float*)d_in[6];
    const float* W2  = (const float*)d_in[7];
    const float* as2 = (const float*)d_in[8];
    const float* ad2 = (const float*)d_in[9];
    const float* b2  = (const float*)d_in[10];
    const float* W3r = (const float*)d_in[11];
    const float* W3l = (const float*)d_in[12];
    const float* b3  = (const float*)d_in[13];
    const float* W4l = (const float*)d_in[14];
    const float* b4l = (const float*)d_in[15];
    const float* W4r = (const float*)d_in[16];
    const float* Wf1 = (const float*)d_in[17];
    const float* bf1 = (const float*)d_in[18];
    const float* Wf2 = (const float*)d_in[19];
    const float* bf2 = (const float*)d_in[20];
    const int* src = ei;
    const int* dst = ei + EE;
    float* out = (float*)d_out;

    static float *p_h = nullptr, *p_acc, *p_x, *p_pool, *p_cnt;
    static int* p_cnt_i;
    if (!p_h) {
        cudaGetSymbolAddress((void**)&p_h, g_h);
        cudaGetSymbolAddress((void**)&p_acc, g_acc);
        cudaGetSymbolAddress((void**)&p_x, g_x);
        cudaGetSymbolAddress((void**)&p_pool, g_pool);
        cudaGetSymbolAddress((void**)&p_cnt, g_cnt);
        cudaGetSymbolAddress((void**)&p_cnt_i, g_cnt_i);
    }

    const int T = 256;
    const int gE    = (EE + T - 1) / T;
    const int gNH   = (NN * HH + T - 1) / T;
    const int gWNN  = (NN * 32 + T - 1) / T;   // warp per node
    const int gQ8   = (NN * 8 + T - 1) / T;    // 8 lanes per node

    // ---- CSR build (shared by all aggregation stages) ----
    cudaMemsetAsync(p_cnt_i, 0, NN * sizeof(int));
    k_count<<<gE, T>>>(dst);
    k_scan<<<1, 1024>>>();
    k_fill<<<gE, T>>>(src, dst);

    // ---- GAT layer 1 ----
    k_gemm128<<<(NN + 15) / 16, 128>>>(x, W1);
    k_attn<<<gNH, T>>>(as1, ad1);
    k_gat_aggr<<<gWNN, T>>>(b1);

    // ---- GAT layer 2 ----
    k_gemm128<<<(NN + 15) / 16, 128>>>(p_x, W2);
    k_attn<<<gNH, T>>>(as2, ad2);
    k_gat_aggr<<<gWNN, T>>>(b2);

    // ---- GraphConv: x3 = relu(segsum(x2[src])@W3r + b3 + x2@W3l) ----
    k_gemm32<HC><<<(NN + 7) / 8, 256>>>(p_x, W3r, p_acc);     // P = x2@W3r
    k_csr_aggr32<<<gQ8, T>>>(p_acc, p_h, 0);                  // sum gather
    k_gemm_add<HC><<<(NN + 7) / 8, 256>>>(p_x, W3l, p_h, b3, p_acc);  // x3

    // ---- SAGEConv: x4 = relu(mean@W4l + b4l + x3@W4r) ----
    k_gemm32<CC><<<(NN + 7) / 8, 256>>>(p_acc, W4l, p_x);     // P2 = x3@W4l
    k_csr_aggr32<<<gQ8, T>>>(p_x, p_h, 1);                    // mean gather
    k_gemm_add<CC><<<(NN + 7) / 8, 256>>>(p_acc, W4r, p_h, b4l, p_x); // x4

    // ---- pool + head ----
    cudaMemsetAsync(p_pool, 0, NGR * CC * sizeof(float));
    cudaMemsetAsync(p_cnt, 0, NGR * sizeof(float));
    k_pool<<<(NN * 8 + T - 1) / T, T>>>(bat, p_x);
    k_head<<<1, 1024>>>(Wf1, bf1, Wf2, bf2, out);
}

// round 4
// speedup vs baseline: 2.0946x; 1.2337x over previous
#include <cuda_runtime.h>

#define NN   50000
#define EE   800000
#define HH   4
#define CC   32
#define HC   128
#define NGR  64
#define NOUT 10
#define NB_SCAN 49   // ceil(NN/1024)

// ---------------- scratch (device globals; no allocation allowed) ------------
__device__ float g_h[NN * HC];     // GAT: h = x@W ; later: proj buffers
__device__ float g_acc[NN * HC];   // later: x3 / proj
__device__ float g_x[NN * HC];     // current node features between layers
__device__ float g_as[NN * HH];
__device__ float g_ad[NN * HH];
__device__ float g_pool[NGR * CC];
__device__ float g_cnt[NGR];
// CSR by destination
__device__ int g_cnt_i[NN];
__device__ int g_rowptr[NN + 1];
__device__ int g_cursor[NN];
__device__ int g_csrc[EE];
__device__ int g_bsum[NB_SCAN];
__device__ int g_boff[NB_SCAN];

__device__ __forceinline__ float lrelu(float v) { return v > 0.f ? v : 0.2f * v; }

// ---------------- CSR build ---------------------------------------------------
__global__ void k_count(const int* __restrict__ dst) {
    int e = blockIdx.x * blockDim.x + threadIdx.x;
    if (e < EE) atomicAdd(&g_cnt_i[dst[e]], 1);
}

// phase 1: per-block (1024 elems) exclusive scan + block sums
__global__ void k_scan1() {
    __shared__ int wsum[32];
    int t = threadIdx.x, b = blockIdx.x;
    int i = b * 1024 + t;
    int v = (i < NN) ? g_cnt_i[i] : 0;
    int incl = v;
#pragma unroll
    for (int o = 1; o < 32; o <<= 1) {
        int n = __shfl_up_sync(0xffffffffu, incl, o);
        if ((t & 31) >= o) incl += n;
    }
    if ((t & 31) == 31) wsum[t >> 5] = incl;
    __syncthreads();
    if (t < 32) {
        int wv = wsum[t];
#pragma unroll
        for (int o = 1; o < 32; o <<= 1) {
            int n = __shfl_up_sync(0xffffffffu, wv, o);
            if (t >= o) wv += n;
        }
        wsum[t] = wv;
    }
    __syncthreads();
    int excl = incl - v + ((t >= 32) ? wsum[(t >> 5) - 1] : 0);
    if (i < NN) g_rowptr[i] = excl;
    if (t == 1023) g_bsum[b] = excl + v;
}

// phase 2: scan the 49 block sums (one 64-thread block)
__global__ void k_scan2() {
    __shared__ int w0s;
    int t = threadIdx.x;
    int v = (t < NB_SCAN) ? g_bsum[t] : 0;
    int incl = v;
#pragma unroll
    for (int o = 1; o < 32; o <<= 1) {
        int n = __shfl_up_sync(0xffffffffu, incl, o);
        if ((t & 31) >= o) incl += n;
    }
    if (t == 31) w0s = incl;
    __syncthreads();
    if (t >= 32) incl += w0s;
    if (t < NB_SCAN) g_boff[t] = incl - v;
}

// phase 3: add block offsets, copy to cursor
__global__ void k_scan3() {
    int i = blockIdx.x * blockDim.x + threadIdx.x;
    if (i < NN) {
        int v = g_rowptr[i] + g_boff[i >> 10];
        g_rowptr[i] = v;
        g_cursor[i] = v;
    }
    if (i == 0) g_rowptr[NN] = EE;
}

__global__ void k_fill(const int* __restrict__ src, const int* __restrict__ dst) {
    int e = blockIdx.x * blockDim.x + threadIdx.x;
    if (e >= EE) return;
    int pos = atomicAdd(&g_cursor[dst[e]], 1);
    g_csrc[pos] = src[e];
}

// ---------------- GEMM + attention epilogue ----------------------------------
// g_h = X@W ; g_as/g_ad = per (node, head) attention logits.
// 64 rows x 128 cols per block; thread (tx,ty) computes 8 rows x 4 cols.
__global__ __launch_bounds__(256) void k_gemm128f(
    const float* __restrict__ X, const float* __restrict__ W,
    const float* __restrict__ aws, const float* __restrict__ awd) {
    __shared__ float Xs[64][HC];
    int t = threadIdx.x, tx = t & 31, ty = t >> 5;
    int row0 = blockIdx.x * 64;
    const float4* Xg = reinterpret_cast<const float4*>(X);
    for (int i = t; i < 64 * 32; i += 256) {
        int r = i >> 5, kq = i & 31;
        int row = row0 + r;
        float4 v = (row < NN) ? Xg[row * 32 + kq] : make_float4(0.f, 0.f, 0.f, 0.f);
        *reinterpret_cast<float4*>(&Xs[r][kq * 4]) = v;
    }
    __syncthreads();
    float acc[8][4];
#pragma unroll
    for (int r = 0; r < 8; r++)
#pragma unroll
        for (int j = 0; j < 4; j++) acc[r][j] = 0.f;
    const float4* W4 = reinterpret_cast<const float4*>(W);
#pragma unroll 4
    for (int k = 0; k < HC; k++) {
        float4 w = __ldg(&W4[k * 32 + tx]);
#pragma unroll
        for (int r = 0; r < 8; r++) {
            float xv = Xs[ty * 8 + r][k];
            acc[r][0] = fmaf(xv, w.x, acc[r][0]);
            acc[r][1] = fmaf(xv, w.y, acc[r][1]);
            acc[r][2] = fmaf(xv, w.z, acc[r][2]);
            acc[r][3] = fmaf(xv, w.w, acc[r][3]);
        }
    }
    // epilogue: write h, compute attention logits via segmented warp reduce
    float4 was = reinterpret_cast<const float4*>(aws)[tx];
    float4 wad = reinterpret_cast<const float4*>(awd)[tx];
    int hd = tx >> 3;
#pragma unroll
    for (int r = 0; r < 8; r++) {
        int row = row0 + ty * 8 + r;
        if (row >= NN) break;  // row is lane-invariant: no divergence
        float4 v = make_float4(acc[r][0], acc[r][1], acc[r][2], acc[r][3]);
        reinterpret_cast<float4*>(g_h)[row * 32 + tx] = v;
        float ps = v.x * was.x + v.y * was.y + v.z * was.z + v.w * was.w;
        float pd = v.x * wad.x + v.y * wad.y + v.z * wad.z + v.w * wad.w;
#pragma unroll
        for (int o = 1; o < 8; o <<= 1) {
            ps += __shfl_xor_sync(0xffffffffu, ps, o);
            pd += __shfl_xor_sync(0xffffffffu, pd, o);
        }
        if ((tx & 7) == 0) {
            g_as[row * HH + hd] = ps;
            g_ad[row * HH + hd] = pd;
        }
    }
}

// ---------------- fused GAT aggregation: warp per dst node --------------------
// softmax (shift-invariant; no max pass needed, logits are O(10)) over in-edges
// + self loop, weighted sum of h, bias, relu -> g_x
__global__ void k_gat_aggr(const float* __restrict__ bias) {
    int w = (blockIdx.x * blockDim.x + threadIdx.x) >> 5;
    if (w >= NN) return;
    int lane = threadIdx.x & 31;
    int row0 = g_rowptr[w], row1 = g_rowptr[w + 1];
    float4 ad4 = reinterpret_cast<const float4*>(g_ad)[w];
    float4 as_self = reinterpret_cast<const float4*>(g_as)[w];
    int hd = lane >> 3;
    float ad_l = (hd == 0) ? ad4.x : (hd == 1) ? ad4.y : (hd == 2) ? ad4.z : ad4.w;
    float4 acc = make_float4(0.f, 0.f, 0.f, 0.f);
    float z = 0.f;
    int s = (row0 < row1) ? g_csrc[row0] : 0;
    for (int k = row0; k < row1; k++) {
        int s_next = (k + 1 < row1) ? g_csrc[k + 1] : 0;
        float4 a = reinterpret_cast<const float4*>(g_as)[s];
        float4 hv = reinterpret_cast<const float4*>(g_h)[s * 32 + lane];
        float as_l = (hd == 0) ? a.x : (hd == 1) ? a.y : (hd == 2) ? a.z : a.w;
        float wgt = __expf(lrelu(as_l + ad_l));
        z += wgt;
        acc.x = fmaf(wgt, hv.x, acc.x);
        acc.y = fmaf(wgt, hv.y, acc.y);
        acc.z = fmaf(wgt, hv.z, acc.z);
        acc.w = fmaf(wgt, hv.w, acc.w);
        s = s_next;
    }
    // self loop
    float as_l = (hd == 0) ? as_self.x : (hd == 1) ? as_self.y : (hd == 2) ? as_self.z : as_self.w;
    float wsf = __expf(lrelu(as_l + ad_l));
    z += wsf;
    float4 hs = reinterpret_cast<const float4*>(g_h)[w * 32 + lane];
    acc.x = fmaf(wsf, hs.x, acc.x);
    acc.y = fmaf(wsf, hs.y, acc.y);
    acc.z = fmaf(wsf, hs.z, acc.z);
    acc.w = fmaf(wsf, hs.w, acc.w);
    float inv = 1.f / (z + 1e-16f);
    float4 b = reinterpret_cast<const float4*>(bias)[lane];
    float4 r;
    r.x = fmaxf(acc.x * inv + b.x, 0.f);
    r.y = fmaxf(acc.y * inv + b.y, 0.f);
    r.z = fmaxf(acc.z * inv + b.z, 0.f);
    r.w = fmaxf(acc.w * inv + b.w, 0.f);
    reinterpret_cast<float4*>(g_x)[w * 32 + lane] = r;
}

// ---------------- CSR gather for 32-wide features (8 lanes / dst) ------------
__global__ void k_csr_aggr32(const float* __restrict__ P, float* __restrict__ Agg,
                             int mean) {
    int q = (blockIdx.x * blockDim.x + threadIdx.x) >> 3;
    if (q >= NN) return;
    int lane = threadIdx.x & 7;
    int row0 = g_rowptr[q], row1 = g_rowptr[q + 1];
    float4 acc = make_float4(0.f, 0.f, 0.f, 0.f);
    for (int k = row0; k < row1; k++) {
        int s = g_csrc[k];
        float4 p = reinterpret_cast<const float4*>(P)[s * 8 + lane];
        acc.x += p.x; acc.y += p.y; acc.z += p.z; acc.w += p.w;
    }
    if (mean) {
        float inv = 1.f / fmaxf((float)(row1 - row0), 1.f);
        acc.x *= inv; acc.y *= inv; acc.z *= inv; acc.w *= inv;
    }
    reinterpret_cast<float4*>(Agg)[q * 8 + lane] = acc;
}

// ---------------- register-tiled 32-wide GEMMs -------------------------------
// 64 rows/block, thread: 8 rows x 1 col (broadcast LDS)
template <int FIN>
__global__ __launch_bounds__(256) void k_gemm32t(
    const float* __restrict__ X, const float* __restrict__ W, float* __restrict__ Y) {
    __shared__ float Xs[64][FIN];
    int t = threadIdx.x, tx = t & 31, ty = t >> 5;
    int row0 = blockIdx.x * 64;
    const float4* Xg = reinterpret_cast<const float4*>(X);
    for (int i = t; i < 64 * (FIN / 4); i += 256) {
        int r = i / (FIN / 4), kq = i % (FIN / 4);
        int row = row0 + r;
        float4 v = (row < NN) ? Xg[row * (FIN / 4) + kq] : make_float4(0.f, 0.f, 0.f, 0.f);
        *reinterpret_cast<float4*>(&Xs[r][kq * 4]) = v;
    }
    __syncthreads();
    float acc[8];
#pragma unroll
    for (int r = 0; r < 8; r++) acc[r] = 0.f;
#pragma unroll 4
    for (int k = 0; k < FIN; k++) {
        float w = __ldg(&W[k * CC + tx]);
#pragma unroll
        for (int r = 0; r < 8; r++) acc[r] = fmaf(Xs[ty * 8 + r][k], w, acc[r]);
    }
#pragma unroll
    for (int r = 0; r < 8; r++) {
        int row = row0 + ty * 8 + r;
        if (row < NN) Y[row * CC + tx] = acc[r];
    }
}

// Y = relu(X@W + D + bias)
template <int FIN>
__global__ __launch_bounds__(256) void k_gemm32t_add(
    const float* __restrict__ X, const float* __restrict__ W,
    const float* __restrict__ D, const float* __restrict__ bias,
    float* __restrict__ Y) {
    __shared__ float Xs[64][FIN];
    int t = threadIdx.x, tx = t & 31, ty = t >> 5;
    int row0 = blockIdx.x * 64;
    const float4* Xg = reinterpret_cast<const float4*>(X);
    for (int i = t; i < 64 * (FIN / 4); i += 256) {
        int r = i / (FIN / 4), kq = i % (FIN / 4);
        int row = row0 + r;
        float4 v = (row < NN) ? Xg[row * (FIN / 4) + kq] : make_float4(0.f, 0.f, 0.f, 0.f);
        *reinterpret_cast<float4*>(&Xs[r][kq * 4]) = v;
    }
    __syncthreads();
    float acc[8];
#pragma unroll
    for (int r = 0; r < 8; r++) acc[r] = 0.f;
#pragma unroll 4
    for (int k = 0; k < FIN; k++) {
        float w = __ldg(&W[k * CC + tx]);
#pragma unroll
        for (int r = 0; r < 8; r++) acc[r] = fmaf(Xs[ty * 8 + r][k], w, acc[r]);
    }
    float b = bias[tx];
#pragma unroll
    for (int r = 0; r < 8; r++) {
        int row = row0 + ty * 8 + r;
        if (row < NN) Y[row * CC + tx] = fmaxf(acc[r] + D[row * CC + tx] + b, 0.f);
    }
}

// ---------------- global mean pool (8 lanes/node, float4 atomics) ------------
__global__ void k_pool(const int* __restrict__ batch, const float* __restrict__ X) {
    int tid = blockIdx.x * blockDim.x + threadIdx.x;
    if (tid >= NN * 8) return;
    int node = tid >> 3, c = tid & 7;
    int b = batch[node];
    float4 v = reinterpret_cast<const float4*>(X)[node * 8 + c];
    atomicAdd(reinterpret_cast<float4*>(g_pool) + b * 8 + c, v);
    if (c == 0) atomicAdd(&g_cnt[b], 1.f);
}

// ---------------- MLP head (single tiny block) -------------------------------
__global__ void k_head(const float* __restrict__ Wf1, const float* __restrict__ bf1,
                       const float* __restrict__ Wf2, const float* __restrict__ bf2,
                       float* __restrict__ out) {
    __shared__ float t1[NGR * CC];
    int t = threadIdx.x;
    for (int idx = t; idx < NGR * CC; idx += blockDim.x) {
        int g = idx >> 5, c = idx & 31;
        float inv = 1.f / fmaxf(g_cnt[g], 1.f);
        float s = 0.f;
#pragma unroll
        for (int k = 0; k < CC; k++) s = fmaf(g_pool[g * CC + k] * inv, Wf1[k * CC + c], s);
        t1[idx] = fmaxf(s + bf1[c], 0.f);
    }
    __syncthreads();
    for (int idx = t; idx < NGR * NOUT; idx += blockDim.x) {
        int g = idx / NOUT, o = idx - g * NOUT;
        float s = 0.f;
#pragma unroll
        for (int k = 0; k < CC; k++) s = fmaf(t1[g * CC + k], Wf2[k * NOUT + o], s);
        out[idx] = s + bf2[o];
    }
}

// =============================================================================
extern "C" void kernel_launch(void* const* d_in, const int* in_sizes, int n_in,
                              void* d_out, int out_size) {
    const float* x   = (const float*)d_in[0];
    const int*   ei  = (const int*)d_in[1];
    const int*   bat = (const int*)d_in[2];
    const float* W1  = (const float*)d_in[3];
    const float* as1 = (const float*)d_in[4];
    const float* ad1 = (const float*)d_in[5];
    const float* b1  = (const float*)d_in[6];
    const float* W2  = (const float*)d_in[7];
    const float* as2 = (const float*)d_in[8];
    const float* ad2 = (const float*)d_in[9];
    const float* b2  = (const float*)d_in[10];
    const float* W3r = (const float*)d_in[11];
    const float* W3l = (const float*)d_in[12];
    const float* b3  = (const float*)d_in[13];
    const float* W4l = (const float*)d_in[14];
    const float* b4l = (const float*)d_in[15];
    const float* W4r = (const float*)d_in[16];
    const float* Wf1 = (const float*)d_in[17];
    const float* bf1 = (const float*)d_in[18];
    const float* Wf2 = (const float*)d_in[19];
    const float* bf2 = (const float*)d_in[20];
    const int* src = ei;
    const int* dst = ei + EE;
    float* out = (float*)d_out;

    static float *p_h = nullptr, *p_acc, *p_x, *p_pool, *p_cnt;
    static int* p_cnt_i;
    if (!p_h) {
        cudaGetSymbolAddress((void**)&p_h, g_h);
        cudaGetSymbolAddress((void**)&p_acc, g_acc);
        cudaGetSymbolAddress((void**)&p_x, g_x);
        cudaGetSymbolAddress((void**)&p_pool, g_pool);
        cudaGetSymbolAddress((void**)&p_cnt, g_cnt);
        cudaGetSymbolAddress((void**)&p_cnt_i, g_cnt_i);
    }

    const int T = 256;
    const int gE    = (EE + T - 1) / T;
    const int gWNN  = (NN * 32 + T - 1) / T;   // warp per node
    const int gQ8   = (NN * 8 + T - 1) / T;    // 8 lanes per node
    const int gR64  = (NN + 63) / 64;          // 64-row tiles

    // ---- CSR build (shared by all aggregation stages) ----
    cudaMemsetAsync(p_cnt_i, 0, NN * sizeof(int));
    k_count<<<gE, T>>>(dst);
    k_scan1<<<NB_SCAN, 1024>>>();
    k_scan2<<<1, 64>>>();
    k_scan3<<<(NN + 1023) / 1024, 1024>>>();
    k_fill<<<gE, T>>>(src, dst);

    // ---- GAT layer 1 ----
    k_gemm128f<<<gR64, 256>>>(x, W1, as1, ad1);
    k_gat_aggr<<<gWNN, T>>>(b1);

    // ---- GAT layer 2 ----
    k_gemm128f<<<gR64, 256>>>(p_x, W2, as2, ad2);
    k_gat_aggr<<<gWNN, T>>>(b2);

    // ---- GraphConv: x3 = relu(segsum(x2[src])@W3r + b3 + x2@W3l) ----
    k_gemm32t<HC><<<gR64, 256>>>(p_x, W3r, p_acc);            // P = x2@W3r
    k_csr_aggr32<<<gQ8, T>>>(p_acc, p_h, 0);                  // sum gather
    k_gemm32t_add<HC><<<gR64, 256>>>(p_x, W3l, p_h, b3, p_acc);  // x3

    // ---- SAGEConv: x4 = relu(mean@W4l + b4l + x3@W4r) ----
    k_gemm32t<CC><<<gR64, 256>>>(p_acc, W4l, p_x);            // P2 = x3@W4l
    k_csr_aggr32<<<gQ8, T>>>(p_x, p_h, 1);                    // mean gather
    k_gemm32t_add<CC><<<gR64, 256>>>(p_acc, W4r, p_h, b4l, p_x); // x4

    // ---- pool + head ----
    cudaMemsetAsync(p_pool, 0, NGR * CC * sizeof(float));
    cudaMemsetAsync(p_cnt, 0, NGR * sizeof(float));
    k_pool<<<(NN * 8 + T - 1) / T, T>>>(bat, p_x);
    k_head<<<1, 1024>>>(Wf1, bf1, Wf2, bf2, out);
}

// round 6
// speedup vs baseline: 2.4662x; 1.1774x over previous
#include <cuda_runtime.h>
#include <cuda_bf16.h>
#include <cstdint>

#define NN   50000
#define EE   800000
#define HH   4
#define CC   32
#define HC   128
#define NGR  64
#define NOUT 10
#define NB_SCAN 49   // ceil(NN/1024)
#define STR  68      // smem row stride in 32-bit words (conflict-free for quad loads)

// ---------------- scratch (device globals; no allocation allowed) ------------
__device__ float g_h[NN * HC];
__device__ float g_acc[NN * HC];
__device__ float g_x[NN * HC];
__device__ float g_as[NN * HH];
__device__ float g_ad[NN * HH];
__device__ float g_pool[NGR * CC];
__device__ float g_cnt[NGR];
// CSR by destination
__device__ int g_cnt_i[NN];
__device__ int g_rowptr[NN + 1];
__device__ int g_cursor[NN];
__device__ int g_csrc[EE];
__device__ int g_bsum[NB_SCAN];
__device__ int g_boff[NB_SCAN];
// bf16-split transposed weights Wt[n][k] per GAT layer
__device__ unsigned short g_WtHi[2][HC * HC];
__device__ unsigned short g_WtLo[2][HC * HC];

__device__ __forceinline__ float lrelu(float v) { return v > 0.f ? v : 0.2f * v; }

// ---------------- W -> bf16 hi/lo transposed prep ----------------------------
__global__ void k_prepWt(const float* __restrict__ W, int layer) {
    int i = blockIdx.x * blockDim.x + threadIdx.x;  // i = k*128 + n
    if (i >= HC * HC) return;
    int k = i >> 7, n = i & 127;
    float w = W[i];
    __nv_bfloat16 hb = __float2bfloat16(w);
    __nv_bfloat16 lb = __float2bfloat16(w - __bfloat162float(hb));
    g_WtHi[layer][n * HC + k] = __bfloat16_as_ushort(hb);
    g_WtLo[layer][n * HC + k] = __bfloat16_as_ushort(lb);
}

// ---------------- mma.sync bf16-split GEMM128 + attention epilogue -----------
#define MMA_BF16(c, A0, A1, A2, A3, B0, B1) \
    asm volatile("mma.sync.aligned.m16n8k16.row.col.f32.bf16.bf16.f32 " \
        "{%0,%1,%2,%3}, {%4,%5,%6,%7}, {%8,%9}, {%0,%1,%2,%3};" \
        : "+f"((c)[0]), "+f"((c)[1]), "+f"((c)[2]), "+f"((c)[3]) \
        : "r"(A0), "r"(A1), "r"(A2), "r"(A3), "r"(B0), "r"(B1))

#define SMEM_MMA (4 * 128 * STR * 4 + 1024)

__global__ __launch_bounds__(256, 1) void k_gemm128mma(
    const float* __restrict__ X, int layer,
    const float* __restrict__ aws, const float* __restrict__ awd) {
    extern __shared__ __align__(16) char smem[];
    uint32_t* xh = reinterpret_cast<uint32_t*>(smem);
    uint32_t* xl = xh + 128 * STR;
    uint32_t* wh = xl + 128 * STR;
    uint32_t* wl = wh + 128 * STR;
    float* sws = reinterpret_cast<float*>(wl + 128 * STR);
    float* swd = sws + 128;
    int tid = threadIdx.x, lane = tid & 31, wid = tid >> 5;
    int gid = lane >> 2, tg = lane & 3;
    int row0 = blockIdx.x * 128;

    if (tid < 128) { sws[tid] = aws[tid]; swd[tid] = awd[tid]; }
    // W images -> smem (row n, words k/2)
    {
        const uint32_t* gh = reinterpret_cast<const uint32_t*>(g_WtHi[layer]);
        const uint32_t* gl = reinterpret_cast<const uint32_t*>(g_WtLo[layer]);
        for (int i = tid; i < 128 * 64; i += 256) {
            int r = i >> 6, w = i & 63;
            wh[r * STR + w] = gh[i];
            wl[r * STR + w] = gl[i];
        }
    }
    // X -> bf16 hi/lo packed words
    {
        const float4* X4 = reinterpret_cast<const float4*>(X);
        for (int i = tid; i < 128 * 32; i += 256) {
            int r = i >> 5, q = i & 31;
            int grow = row0 + r;
            float4 v = (grow < NN) ? X4[(size_t)grow * 32 + q] : make_float4(0.f, 0.f, 0.f, 0.f);
            float vv[4] = {v.x, v.y, v.z, v.w};
#pragma unroll
            for (int q2 = 0; q2 < 2; q2++) {
                __nv_bfloat16 h0 = __float2bfloat16(vv[2 * q2]);
                __nv_bfloat16 h1 = __float2bfloat16(vv[2 * q2 + 1]);
                __nv_bfloat16 l0 = __float2bfloat16(vv[2 * q2] - __bfloat162float(h0));
                __nv_bfloat16 l1 = __float2bfloat16(vv[2 * q2 + 1] - __bfloat162float(h1));
                xh[r * STR + 2 * q + q2] =
                    ((uint32_t)__bfloat16_as_ushort(h1) << 16) | __bfloat16_as_ushort(h0);
                xl[r * STR + 2 * q + q2] =
                    ((uint32_t)__bfloat16_as_ushort(l1) << 16) | __bfloat16_as_ushort(l0);
            }
        }
    }
    __syncthreads();

    float acc[16][4];
#pragma unroll
    for (int t = 0; t < 16; t++)
#pragma unroll
        for (int j = 0; j < 4; j++) acc[t][j] = 0.f;

    int m0 = wid * 16;
    const uint32_t* xrh = xh + (m0 + gid) * STR + tg;
    const uint32_t* xrl = xl + (m0 + gid) * STR + tg;
#pragma unroll 1
    for (int kk = 0; kk < 8; kk++) {
        int kw = kk * 8;
        uint32_t ah0 = xrh[kw],           ah2 = xrh[kw + 4];
        uint32_t ah1 = xrh[kw + 8 * STR], ah3 = xrh[kw + 8 * STR + 4];
        uint32_t al0 = xrl[kw],           al2 = xrl[kw + 4];
        uint32_t al1 = xrl[kw + 8 * STR], al3 = xrl[kw + 8 * STR + 4];
#pragma unroll
        for (int t = 0; t < 16; t++) {
            const uint32_t* wrh = wh + (t * 8 + gid) * STR + kw + tg;
            const uint32_t* wrl = wl + (t * 8 + gid) * STR + kw + tg;
            uint32_t bh0 = wrh[0], bh1 = wrh[4];
            uint32_t bl0 = wrl[0], bl1 = wrl[4];
            MMA_BF16(acc[t], ah0, ah1, ah2, ah3, bh0, bh1);
            MMA_BF16(acc[t], ah0, ah1, ah2, ah3, bl0, bl1);
            MMA_BF16(acc[t], al0, al1, al2, al3, bh0, bh1);
        }
    }

    // epilogue: store h rows + attention logits
    int r0 = row0 + m0 + gid, r1 = r0 + 8;
#pragma unroll
    for (int t = 0; t < 16; t++) {
        int col = t * 8 + 2 * tg;
        if (r0 < NN) *reinterpret_cast<float2*>(&g_h[(size_t)r0 * HC + col]) =
            make_float2(acc[t][0], acc[t][1]);
        if (r1 < NN) *reinterpret_cast<float2*>(&g_h[(size_t)r1 * HC + col]) =
            make_float2(acc[t][2], acc[t][3]);
    }
#pragma unroll
    for (int h = 0; h < 4; h++) {
        float ps0 = 0.f, pd0 = 0.f, ps1 = 0.f, pd1 = 0.f;
#pragma unroll
        for (int j = 0; j < 4; j++) {
            int t = 4 * h + j;
            int col = t * 8 + 2 * tg;
            float w0 = sws[col], w1 = sws[col + 1];
            float v0 = swd[col], v1 = swd[col + 1];
            ps0 = fmaf(acc[t][0], w0, fmaf(acc[t][1], w1, ps0));
            pd0 = fmaf(acc[t][0], v0, fmaf(acc[t][1], v1, pd0));
            ps1 = fmaf(acc[t][2], w0, fmaf(acc[t][3], w1, ps1));
            pd1 = fmaf(acc[t][2], v0, fmaf(acc[t][3], v1, pd1));
        }
#pragma unroll
        for (int o = 1; o <= 2; o <<= 1) {
            ps0 += __shfl_xor_sync(0xffffffffu, ps0, o);
            pd0 += __shfl_xor_sync(0xffffffffu, pd0, o);
            ps1 += __shfl_xor_sync(0xffffffffu, ps1, o);
            pd1 += __shfl_xor_sync(0xffffffffu, pd1, o);
        }
        if (tg == 0) {
            if (r0 < NN) { g_as[r0 * HH + h] = ps0; g_ad[r0 * HH + h] = pd0; }
            if (r1 < NN) { g_as[r1 * HH + h] = ps1; g_ad[r1 * HH + h] = pd1; }
        }
    }
}

// ---------------- CSR build ---------------------------------------------------
__global__ void k_count(const int* __restrict__ dst) {
    int e = blockIdx.x * blockDim.x + threadIdx.x;
    if (e < EE) atomicAdd(&g_cnt_i[dst[e]], 1);
}

__global__ void k_scan1() {
    __shared__ int wsum[32];
    int t = threadIdx.x, b = blockIdx.x;
    int i = b * 1024 + t;
    int v = (i < NN) ? g_cnt_i[i] : 0;
    int incl = v;
#pragma unroll
    for (int o = 1; o < 32; o <<= 1) {
        int n = __shfl_up_sync(0xffffffffu, incl, o);
        if ((t & 31) >= o) incl += n;
    }
    if ((t & 31) == 31) wsum[t >> 5] = incl;
    __syncthreads();
    if (t < 32) {
        int wv = wsum[t];
#pragma unroll
        for (int o = 1; o < 32; o <<= 1) {
            int n = __shfl_up_sync(0xffffffffu, wv, o);
            if (t >= o) wv += n;
        }
        wsum[t] = wv;
    }
    __syncthreads();
    int excl = incl - v + ((t >= 32) ? wsum[(t >> 5) - 1] : 0);
    if (i < NN) g_rowptr[i] = excl;
    if (t == 1023) g_bsum[b] = excl + v;
}

__global__ void k_scan2() {
    __shared__ int w0s;
    int t = threadIdx.x;
    int v = (t < NB_SCAN) ? g_bsum[t] : 0;
    int incl = v;
#pragma unroll
    for (int o = 1; o < 32; o <<= 1) {
        int n = __shfl_up_sync(0xffffffffu, incl, o);
        if ((t & 31) >= o) incl += n;
    }
    if (t == 31) w0s = incl;
    __syncthreads();
    if (t >= 32) incl += w0s;
    if (t < NB_SCAN) g_boff[t] = incl - v;
}

__global__ void k_scan3() {
    int i = blockIdx.x * blockDim.x + threadIdx.x;
    if (i < NN) {
        int v = g_rowptr[i] + g_boff[i >> 10];
        g_rowptr[i] = v;
        g_cursor[i] = v;
    }
    if (i == 0) g_rowptr[NN] = EE;
}

__global__ void k_fill(const int* __restrict__ src, const int* __restrict__ dst) {
    int e = blockIdx.x * blockDim.x + threadIdx.x;
    if (e >= EE) return;
    int pos = atomicAdd(&g_cursor[dst[e]], 1);
    g_csrc[pos] = src[e];
}

// ---------------- fused GAT aggregation: warp per dst node --------------------
__global__ void k_gat_aggr(const float* __restrict__ bias) {
    int w = (blockIdx.x * blockDim.x + threadIdx.x) >> 5;
    if (w >= NN) return;
    int lane = threadIdx.x & 31;
    int row0 = g_rowptr[w], row1 = g_rowptr[w + 1];
    float4 ad4 = reinterpret_cast<const float4*>(g_ad)[w];
    float4 as_self = reinterpret_cast<const float4*>(g_as)[w];
    int hd = lane >> 3;
    float ad_l = (hd == 0) ? ad4.x : (hd == 1) ? ad4.y : (hd == 2) ? ad4.z : ad4.w;
    float4 acc = make_float4(0.f, 0.f, 0.f, 0.f);
    float z = 0.f;
    int s = (row0 < row1) ? g_csrc[row0] : 0;
    for (int k = row0; k < row1; k++) {
        int s_next = (k + 1 < row1) ? g_csrc[k + 1] : 0;
        float4 a = reinterpret_cast<const float4*>(g_as)[s];
        float4 hv = reinterpret_cast<const float4*>(g_h)[s * 32 + lane];
        float as_l = (hd == 0) ? a.x : (hd == 1) ? a.y : (hd == 2) ? a.z : a.w;
        float wgt = __expf(lrelu(as_l + ad_l));
        z += wgt;
        acc.x = fmaf(wgt, hv.x, acc.x);
        acc.y = fmaf(wgt, hv.y, acc.y);
        acc.z = fmaf(wgt, hv.z, acc.z);
        acc.w = fmaf(wgt, hv.w, acc.w);
        s = s_next;
    }
    float as_l = (hd == 0) ? as_self.x : (hd == 1) ? as_self.y : (hd == 2) ? as_self.z : as_self.w;
    float wsf = __expf(lrelu(as_l + ad_l));
    z += wsf;
    float4 hs = reinterpret_cast<const float4*>(g_h)[w * 32 + lane];
    acc.x = fmaf(wsf, hs.x, acc.x);
    acc.y = fmaf(wsf, hs.y, acc.y);
    acc.z = fmaf(wsf, hs.z, acc.z);
    acc.w = fmaf(wsf, hs.w, acc.w);
    float inv = 1.f / (z + 1e-16f);
    float4 b = reinterpret_cast<const float4*>(bias)[lane];
    float4 r;
    r.x = fmaxf(acc.x * inv + b.x, 0.f);
    r.y = fmaxf(acc.y * inv + b.y, 0.f);
    r.z = fmaxf(acc.z * inv + b.z, 0.f);
    r.w = fmaxf(acc.w * inv + b.w, 0.f);
    reinterpret_cast<float4*>(g_x)[w * 32 + lane] = r;
}

// ---------------- CSR gather for 32-wide features (8 lanes / dst) ------------
__global__ void k_csr_aggr32(const float* __restrict__ P, float* __restrict__ Agg,
                             int mean) {
    int q = (blockIdx.x * blockDim.x + threadIdx.x) >> 3;
    if (q >= NN) return;
    int lane = threadIdx.x & 7;
    int row0 = g_rowptr[q], row1 = g_rowptr[q + 1];
    float4 acc = make_float4(0.f, 0.f, 0.f, 0.f);
    for (int k = row0; k < row1; k++) {
        int s = g_csrc[k];
        float4 p = reinterpret_cast<const float4*>(P)[s * 8 + lane];
        acc.x += p.x; acc.y += p.y; acc.z += p.z; acc.w += p.w;
    }
    if (mean) {
        float inv = 1.f / fmaxf((float)(row1 - row0), 1.f);
        acc.x *= inv; acc.y *= inv; acc.z *= inv; acc.w *= inv;
    }
    reinterpret_cast<float4*>(Agg)[q * 8 + lane] = acc;
}

// ---------------- fused dual projection: Ya = X@Wa, Yb = X@Wb ----------------
template <int FIN>
__global__ __launch_bounds__(256) void k_proj2(
    const float* __restrict__ X, const float* __restrict__ Wa,
    const float* __restrict__ Wb, float* __restrict__ Ya, float* __restrict__ Yb) {
    __shared__ float Xs[64][FIN];
    int t = threadIdx.x, tx = t & 31, ty = t >> 5;
    int row0 = blockIdx.x * 64;
    const float4* Xg = reinterpret_cast<const float4*>(X);
    for (int i = t; i < 64 * (FIN / 4); i += 256) {
        int r = i / (FIN / 4), kq = i % (FIN / 4);
        int row = row0 + r;
        float4 v = (row < NN) ? Xg[row * (FIN / 4) + kq] : make_float4(0.f, 0.f, 0.f, 0.f);
        *reinterpret_cast<float4*>(&Xs[r][kq * 4]) = v;
    }
    __syncthreads();
    float a[8], b[8];
#pragma unroll
    for (int r = 0; r < 8; r++) { a[r] = 0.f; b[r] = 0.f; }
#pragma unroll 4
    for (int k = 0; k < FIN; k++) {
        float wa = __ldg(&Wa[k * CC + tx]);
        float wb = __ldg(&Wb[k * CC + tx]);
#pragma unroll
        for (int r = 0; r < 8; r++) {
            float xv = Xs[ty * 8 + r][k];
            a[r] = fmaf(xv, wa, a[r]);
            b[r] = fmaf(xv, wb, b[r]);
        }
    }
#pragma unroll
    for (int r = 0; r < 8; r++) {
        int row = row0 + ty * 8 + r;
        if (row < NN) {
            Ya[row * CC + tx] = a[r];
            Yb[row * CC + tx] = b[r];
        }
    }
}

// ---------------- elementwise combine: Y = relu(A + B + bias) ----------------
__global__ void k_combine(const float* __restrict__ A, const float* __restrict__ B,
                          const float* __restrict__ bias, float* __restrict__ Y) {
    int tid = blockIdx.x * blockDim.x + threadIdx.x;
    if (tid >= NN * 8) return;
    int c = tid & 7;
    float4 a = reinterpret_cast<const float4*>(A)[tid];
    float4 b = reinterpret_cast<const float4*>(B)[tid];
    float4 bb = reinterpret_cast<const float4*>(bias)[c];
    float4 r;
    r.x = fmaxf(a.x + b.x + bb.x, 0.f);
    r.y = fmaxf(a.y + b.y + bb.y, 0.f);
    r.z = fmaxf(a.z + b.z + bb.z, 0.f);
    r.w = fmaxf(a.w + b.w + bb.w, 0.f);
    reinterpret_cast<float4*>(Y)[tid] = r;
}

// ---------------- global mean pool (8 lanes/node, float4 atomics) ------------
__global__ void k_pool(const int* __restrict__ batch, const float* __restrict__ X) {
    int tid = blockIdx.x * blockDim.x + threadIdx.x;
    if (tid >= NN * 8) return;
    int node = tid >> 3, c = tid & 7;
    int b = batch[node];
    float4 v = reinterpret_cast<const float4*>(X)[node * 8 + c];
    atomicAdd(reinterpret_cast<float4*>(g_pool) + b * 8 + c, v);
    if (c == 0) atomicAdd(&g_cnt[b], 1.f);
}

// ---------------- MLP head (single tiny block) -------------------------------
__global__ void k_head(const float* __restrict__ Wf1, const float* __restrict__ bf1,
                       const float* __restrict__ Wf2, const float* __restrict__ bf2,
                       float* __restrict__ out) {
    __shared__ float t1[NGR * CC];
    int t = threadIdx.x;
    for (int idx = t; idx < NGR * CC; idx += blockDim.x) {
        int g = idx >> 5, c = idx & 31;
        float inv = 1.f / fmaxf(g_cnt[g], 1.f);
        float s = 0.f;
#pragma unroll
        for (int k = 0; k < CC; k++) s = fmaf(g_pool[g * CC + k] * inv, Wf1[k * CC + c], s);
        t1[idx] = fmaxf(s + bf1[c], 0.f);
    }
    __syncthreads();
    for (int idx = t; idx < NGR * NOUT; idx += blockDim.x) {
        int g = idx / NOUT, o = idx - g * NOUT;
        float s = 0.f;
#pragma unroll
        for (int k = 0; k < CC; k++) s = fmaf(t1[g * CC + k], Wf2[k * NOUT + o], s);
        out[idx] = s + bf2[o];
    }
}

// =============================================================================
extern "C" void kernel_launch(void* const* d_in, const int* in_sizes, int n_in,
                              void* d_out, int out_size) {
    const float* x   = (const float*)d_in[0];
    const int*   ei  = (const int*)d_in[1];
    const int*   bat = (const int*)d_in[2];
    const float* W1  = (const float*)d_in[3];
    const float* as1 = (const float*)d_in[4];
    const float* ad1 = (const float*)d_in[5];
    const float* b1  = (const float*)d_in[6];
    const float* W2  = (const float*)d_in[7];
    const float* as2 = (const float*)d_in[8];
    const float* ad2 = (const float*)d_in[9];
    const float* b2  = (const float*)d_in[10];
    const float* W3r = (const float*)d_in[11];
    const float* W3l = (const float*)d_in[12];
    const float* b3  = (const float*)d_in[13];
    const float* W4l = (const float*)d_in[14];
    const float* b4l = (const float*)d_in[15];
    const float* W4r = (const float*)d_in[16];
    const float* Wf1 = (const float*)d_in[17];
    const float* bf1 = (const float*)d_in[18];
    const float* Wf2 = (const float*)d_in[19];
    const float* bf2 = (const float*)d_in[20];
    const int* src = ei;
    const int* dst = ei + EE;
    float* out = (float*)d_out;

    static float *p_h = nullptr, *p_acc, *p_x, *p_pool, *p_cnt;
    static int* p_cnt_i;
    static bool attr_done = false;
    if (!p_h) {
        cudaGetSymbolAddress((void**)&p_h, g_h);
        cudaGetSymbolAddress((void**)&p_acc, g_acc);
        cudaGetSymbolAddress((void**)&p_x, g_x);
        cudaGetSymbolAddress((void**)&p_pool, g_pool);
        cudaGetSymbolAddress((void**)&p_cnt, g_cnt);
        cudaGetSymbolAddress((void**)&p_cnt_i, g_cnt_i);
    }
    if (!attr_done) {
        cudaFuncSetAttribute(k_gemm128mma, cudaFuncAttributeMaxDynamicSharedMemorySize, SMEM_MMA);
        attr_done = true;
    }

    const int T = 256;
    const int gE    = (EE + T - 1) / T;
    const int gWNN  = (NN * 32 + T - 1) / T;   // warp per node
    const int gQ8   = (NN * 8 + T - 1) / T;    // 8 lanes per node
    const int gR64  = (NN + 63) / 64;          // 64-row tiles
    const int gTC   = (NN + 127) / 128;        // 128-row MMA tiles

    // ---- W prep (bf16 split, transposed) + CSR build ----
    k_prepWt<<<(HC * HC + T - 1) / T, T>>>(W1, 0);
    k_prepWt<<<(HC * HC + T - 1) / T, T>>>(W2, 1);
    cudaMemsetAsync(p_cnt_i, 0, NN * sizeof(int));
    k_count<<<gE, T>>>(dst);
    k_scan1<<<NB_SCAN, 1024>>>();
    k_scan2<<<1, 64>>>();
    k_scan3<<<(NN + 1023) / 1024, 1024>>>();
    k_fill<<<gE, T>>>(src, dst);

    // ---- GAT layer 1 ----
    k_gemm128mma<<<gTC, 256, SMEM_MMA>>>(x, 0, as1, ad1);
    k_gat_aggr<<<gWNN, T>>>(b1);

    // ---- GAT layer 2 ----
    k_gemm128mma<<<gTC, 256, SMEM_MMA>>>(p_x, 1, as2, ad2);
    k_gat_aggr<<<gWNN, T>>>(b2);

    // ---- GraphConv: x3 = relu(segsum((x2@W3r)[src]) + x2@W3l + b3) ----
    k_proj2<HC><<<gR64, 256>>>(p_x, W3r, W3l, p_acc, p_h);   // P=g_acc, Q=g_h
    k_csr_aggr32<<<gQ8, T>>>(p_acc, p_x, 0);                 // Agg -> g_x
    k_combine<<<gQ8, T>>>(p_x, p_h, b3, p_acc);              // x3 -> g_acc

    // ---- SAGEConv: x4 = relu(mean((x3@W4l)[src]) + x3@W4r + b4l) ----
    k_proj2<CC><<<gR64, 256>>>(p_acc, W4l, W4r, p_x, p_h);   // P2=g_x, R=g_h
    k_csr_aggr32<<<gQ8, T>>>(p_x, p_acc, 1);                 // mean -> g_acc
    k_combine<<<gQ8, T>>>(p_acc, p_h, b4l, p_x);             // x4 -> g_x

    // ---- pool + head ----
    cudaMemsetAsync(p_pool, 0, NGR * CC * sizeof(float));
    cudaMemsetAsync(p_cnt, 0, NGR * sizeof(float));
    k_pool<<<(NN * 8 + T - 1) / T, T>>>(bat, p_x);
    k_head<<<1, 1024>>>(Wf1, bf1, Wf2, bf2, out);
}